// round 15
// baseline (speedup 1.0000x reference)
#include <cuda_runtime.h>
#include <math.h>

#define FIXED_FRAMES 30
#define N_SEL 107
#define N_LM 543
#define RED_BLOCKS 296
#define RED_THREADS 1024

__constant__ int c_sel[N_SEL] = {
    61,185,40,39,37,0,267,269,270,409,291,
    146,91,181,84,17,314,405,321,375,
    78,191,80,81,82,13,312,311,310,415,
    95,88,178,87,14,317,402,318,324,308,
    468,469,470,471,472,473,474,475,476,477,478,479,480,481,482,483,484,485,486,487,488,
    489,490,491,492,493,494,495,496,497,498,499,500,501,502,503,504,505,506,507,508,509,510,511,512,513,
    522,523,524,525,526,527,528,529,530,531,532,533,534,535,536,537,538,539,540,541,542
};

// Per-block partials: written unconditionally every launch — no init needed.
__device__ float g_psum[RED_BLOCKS];
__device__ float g_psumsq[RED_BLOCKS];
__device__ int   g_pcnt[RED_BLOCKS];

struct F8 { float v[8]; };

// 256-bit global load (LDG.E.256 on sm_100): fewer LSU issues per byte.
__device__ __forceinline__ F8 ldg256(const float* p) {
    unsigned int a, b, c, d, e, f, g, h;
    asm("ld.global.v8.b32 {%0,%1,%2,%3,%4,%5,%6,%7}, [%8];"
        : "=r"(a), "=r"(b), "=r"(c), "=r"(d),
          "=r"(e), "=r"(f), "=r"(g), "=r"(h)
        : "l"(p));
    F8 r;
    r.v[0] = __uint_as_float(a); r.v[1] = __uint_as_float(b);
    r.v[2] = __uint_as_float(c); r.v[3] = __uint_as_float(d);
    r.v[4] = __uint_as_float(e); r.v[5] = __uint_as_float(f);
    r.v[6] = __uint_as_float(g); r.v[7] = __uint_as_float(h);
    return r;
}

__global__ void __launch_bounds__(RED_THREADS) reduce_kernel(
        const float* __restrict__ x, long long nvec8, long long ntotal) {
    float s = 0.0f, q = 0.0f;
    int cnt = 0;

    const long long stride = (long long)gridDim.x * blockDim.x;
    long long i = (long long)blockIdx.x * blockDim.x + threadIdx.x;

    #define ACC8(r) { \
        _Pragma("unroll") \
        for (int k = 0; k < 8; k++) { \
            float v = r.v[k]; \
            float t = (v == v) ? v : 0.0f; \
            cnt += (v == v); \
            s += t; \
            q += t * t; \
        } }

    // 2-deep batched 32B loads = 64B in flight per thread (best-measured shape)
    for (; i + stride < nvec8; i += 2 * stride) {
        F8 a = ldg256(x + i * 8);
        F8 b = ldg256(x + (i + stride) * 8);
        ACC8(a); ACC8(b);
    }
    for (; i < nvec8; i += stride) {
        F8 a = ldg256(x + i * 8);
        ACC8(a);
    }
    #undef ACC8

    // scalar tail (elements beyond nvec8*8)
    if (blockIdx.x == 0 && threadIdx.x == 0) {
        for (long long t = nvec8 * 8; t < ntotal; t++) {
            float v = x[t];
            if (v == v) { s += v; q += v * v; cnt += 1; }
        }
    }

    // block reduce (1024 threads = 32 warps)
    for (int off = 16; off; off >>= 1) {
        s   += __shfl_down_sync(0xFFFFFFFFu, s, off);
        q   += __shfl_down_sync(0xFFFFFFFFu, q, off);
        cnt += __shfl_down_sync(0xFFFFFFFFu, cnt, off);
    }
    __shared__ float ss[32], sq[32];
    __shared__ int sc[32];
    int wid = threadIdx.x >> 5;
    int lid = threadIdx.x & 31;
    if (lid == 0) { ss[wid] = s; sq[wid] = q; sc[wid] = cnt; }
    __syncthreads();
    if (wid == 0) {
        s   = ss[lid];
        q   = sq[lid];
        cnt = sc[lid];
        for (int off = 16; off; off >>= 1) {
            s   += __shfl_down_sync(0xFFFFFFFFu, s, off);
            q   += __shfl_down_sync(0xFFFFFFFFu, q, off);
            cnt += __shfl_down_sync(0xFFFFFFFFu, cnt, off);
        }
        if (lid == 0) {
            g_psum[blockIdx.x]   = s;
            g_psumsq[blockIdx.x] = q;
            g_pcnt[blockIdx.x]   = cnt;
        }
    }
}

// Each block redundantly reduces the partials (L2-hot, ~3.5KB), then
// writes its slice of the [30, 107, 3] output (one thread per element).
__global__ void __launch_bounds__(1024) gather_kernel(
        const float* __restrict__ x, float* __restrict__ out, int T) {
    __shared__ double s_red[64];
    __shared__ long long s_redc[32];
    __shared__ float s_mean, s_invstd;

    {
        double s = 0.0, q = 0.0;
        long long c = 0;
        int t = threadIdx.x;
        if (t < RED_BLOCKS) { s += g_psum[t]; q += g_psumsq[t]; c += g_pcnt[t]; }

        for (int off = 16; off; off >>= 1) {
            s += __shfl_down_sync(0xFFFFFFFFu, s, off);
            q += __shfl_down_sync(0xFFFFFFFFu, q, off);
            c += __shfl_down_sync(0xFFFFFFFFu, c, off);
        }
        int wid = threadIdx.x >> 5;
        int lid = threadIdx.x & 31;
        if (lid == 0) { s_red[wid] = s; s_red[32 + wid] = q; s_redc[wid] = c; }
        __syncthreads();
        if (wid == 0) {
            s = s_red[lid];
            q = s_red[32 + lid];
            c = s_redc[lid];
            for (int off = 16; off; off >>= 1) {
                s += __shfl_down_sync(0xFFFFFFFFu, s, off);
                q += __shfl_down_sync(0xFFFFFFFFu, q, off);
                c += __shfl_down_sync(0xFFFFFFFFu, c, off);
            }
            if (lid == 0) {
                double cn = (double)c;
                double mean = s / cn;
                double var = (q - s * s / cn) / (cn - 1.0);
                s_mean = (float)mean;
                s_invstd = (float)(1.0 / sqrt(var));
            }
        }
        __syncthreads();
    }

    float meanf = s_mean;
    float inv_std = s_invstd;

    const int OUT_N = FIXED_FRAMES * N_SEL * 3;
    int i = blockIdx.x * blockDim.x + threadIdx.x;
    if (i >= OUT_N) return;

    int f = i / (N_SEL * 3);
    int rem = i - f * (N_SEL * 3);
    int l = rem / 3;
    int c = rem - l * 3;
    int lm = c_sel[l];

    if (T >= FIXED_FRAMES) {
        // nearest-exact (f32 arithmetic matching the reference)
        float scale = (float)((double)T / (double)FIXED_FRAMES);
        float pos = ((float)f + 0.5f) * scale;
        int idx = (int)floorf(pos);
        if (idx < 0) idx = 0;
        if (idx > T - 1) idx = T - 1;
        float v = x[(size_t)idx * (N_LM * 3) + lm * 3 + c];
        out[i] = (v == v) ? (v - meanf) * inv_std : 0.0f;
    } else {
        // linear, align_corners=False
        float scale = (float)((double)T / (double)FIXED_FRAMES);
        float pos = ((float)f + 0.5f) * scale - 0.5f;
        pos = fminf(fmaxf(pos, 0.0f), (float)(T - 1));
        int i0 = (int)floorf(pos);
        int i1 = min(i0 + 1, T - 1);
        float w = pos - (float)i0;
        float v0 = x[(size_t)i0 * (N_LM * 3) + lm * 3 + c];
        float v1 = x[(size_t)i1 * (N_LM * 3) + lm * 3 + c];
        float y0 = (v0 == v0) ? (v0 - meanf) * inv_std : 0.0f;
        float y1 = (v1 == v1) ? (v1 - meanf) * inv_std : 0.0f;
        out[i] = (1.0f - w) * y0 + w * y1;
    }
}

extern "C" void kernel_launch(void* const* d_in, const int* in_sizes, int n_in,
                              void* d_out, int out_size) {
    const float* x = (const float*)d_in[0];
    float* out = (float*)d_out;

    long long ntotal = (long long)in_sizes[0];
    int T = (int)(ntotal / (N_LM * 3));
    long long nvec8 = ntotal >> 3;   // 256-bit chunks

    reduce_kernel<<<RED_BLOCKS, RED_THREADS>>>(x, nvec8, ntotal);

    const int OUT_N = FIXED_FRAMES * N_SEL * 3;  // 9630
    gather_kernel<<<(OUT_N + 1023) / 1024, 1024>>>(x, out, T);
}

// round 17
// speedup vs baseline: 1.2960x; 1.2960x over previous
#include <cuda_runtime.h>
#include <math.h>

#define FIXED_FRAMES 30
#define N_SEL 107
#define N_LM 543
#define RED_BLOCKS 444
#define RED_THREADS 512

__constant__ int c_sel[N_SEL] = {
    61,185,40,39,37,0,267,269,270,409,291,
    146,91,181,84,17,314,405,321,375,
    78,191,80,81,82,13,312,311,310,415,
    95,88,178,87,14,317,402,318,324,308,
    468,469,470,471,472,473,474,475,476,477,478,479,480,481,482,483,484,485,486,487,488,
    489,490,491,492,493,494,495,496,497,498,499,500,501,502,503,504,505,506,507,508,509,510,511,512,513,
    522,523,524,525,526,527,528,529,530,531,532,533,534,535,536,537,538,539,540,541,542
};

// Per-block partials: written unconditionally every launch — no init needed.
__device__ float g_psum[RED_BLOCKS];
__device__ float g_psumsq[RED_BLOCKS];
__device__ int   g_pcnt[RED_BLOCKS];

struct F8 { float v[8]; };

// 256-bit global load (LDG.E.256 on sm_100): fewer LSU issues per byte.
__device__ __forceinline__ F8 ldg256(const float* p) {
    unsigned int a, b, c, d, e, f, g, h;
    asm("ld.global.v8.b32 {%0,%1,%2,%3,%4,%5,%6,%7}, [%8];"
        : "=r"(a), "=r"(b), "=r"(c), "=r"(d),
          "=r"(e), "=r"(f), "=r"(g), "=r"(h)
        : "l"(p));
    F8 r;
    r.v[0] = __uint_as_float(a); r.v[1] = __uint_as_float(b);
    r.v[2] = __uint_as_float(c); r.v[3] = __uint_as_float(d);
    r.v[4] = __uint_as_float(e); r.v[5] = __uint_as_float(f);
    r.v[6] = __uint_as_float(g); r.v[7] = __uint_as_float(h);
    return r;
}

__global__ void __launch_bounds__(RED_THREADS) reduce_kernel(
        const float* __restrict__ x, long long nvec8, long long ntotal) {
    float s = 0.0f, q = 0.0f;
    int cnt = 0;

    const long long stride = (long long)gridDim.x * blockDim.x;
    long long i = (long long)blockIdx.x * blockDim.x + threadIdx.x;

    #define ACC8(r) { \
        _Pragma("unroll") \
        for (int k = 0; k < 8; k++) { \
            float v = r.v[k]; \
            float t = (v == v) ? v : 0.0f; \
            cnt += (v == v); \
            s += t; \
            q += t * t; \
        } }

    // 2-deep batched 32B loads = 64B in flight per thread (best-measured shape)
    for (; i + stride < nvec8; i += 2 * stride) {
        F8 a = ldg256(x + i * 8);
        F8 b = ldg256(x + (i + stride) * 8);
        ACC8(a); ACC8(b);
    }
    for (; i < nvec8; i += stride) {
        F8 a = ldg256(x + i * 8);
        ACC8(a);
    }
    #undef ACC8

    // scalar tail (elements beyond nvec8*8)
    if (blockIdx.x == 0 && threadIdx.x == 0) {
        for (long long t = nvec8 * 8; t < ntotal; t++) {
            float v = x[t];
            if (v == v) { s += v; q += v * v; cnt += 1; }
        }
    }

    // block reduce (512 threads = 16 warps)
    for (int off = 16; off; off >>= 1) {
        s   += __shfl_down_sync(0xFFFFFFFFu, s, off);
        q   += __shfl_down_sync(0xFFFFFFFFu, q, off);
        cnt += __shfl_down_sync(0xFFFFFFFFu, cnt, off);
    }
    __shared__ float ss[16], sq[16];
    __shared__ int sc[16];
    int wid = threadIdx.x >> 5;
    int lid = threadIdx.x & 31;
    if (lid == 0) { ss[wid] = s; sq[wid] = q; sc[wid] = cnt; }
    __syncthreads();
    if (wid == 0) {
        s   = (lid < (RED_THREADS >> 5)) ? ss[lid] : 0.0f;
        q   = (lid < (RED_THREADS >> 5)) ? sq[lid] : 0.0f;
        cnt = (lid < (RED_THREADS >> 5)) ? sc[lid] : 0;
        for (int off = 8; off; off >>= 1) {
            s   += __shfl_down_sync(0xFFFFFFFFu, s, off);
            q   += __shfl_down_sync(0xFFFFFFFFu, q, off);
            cnt += __shfl_down_sync(0xFFFFFFFFu, cnt, off);
        }
        if (lid == 0) {
            g_psum[blockIdx.x]   = s;
            g_psumsq[blockIdx.x] = q;
            g_pcnt[blockIdx.x]   = cnt;
        }
    }
}

// Each block redundantly reduces the partials (L2-hot, ~5.3KB), then
// writes its slice of the [30, 107, 3] output (one thread per element).
__global__ void __launch_bounds__(1024) gather_kernel(
        const float* __restrict__ x, float* __restrict__ out, int T) {
    __shared__ double s_red[64];
    __shared__ long long s_redc[32];
    __shared__ float s_mean, s_invstd;

    {
        double s = 0.0, q = 0.0;
        long long c = 0;
        int t = threadIdx.x;
        if (t < RED_BLOCKS) { s += g_psum[t]; q += g_psumsq[t]; c += g_pcnt[t]; }

        for (int off = 16; off; off >>= 1) {
            s += __shfl_down_sync(0xFFFFFFFFu, s, off);
            q += __shfl_down_sync(0xFFFFFFFFu, q, off);
            c += __shfl_down_sync(0xFFFFFFFFu, c, off);
        }
        int wid = threadIdx.x >> 5;
        int lid = threadIdx.x & 31;
        if (lid == 0) { s_red[wid] = s; s_red[32 + wid] = q; s_redc[wid] = c; }
        __syncthreads();
        if (wid == 0) {
            s = s_red[lid];
            q = s_red[32 + lid];
            c = s_redc[lid];
            for (int off = 16; off; off >>= 1) {
                s += __shfl_down_sync(0xFFFFFFFFu, s, off);
                q += __shfl_down_sync(0xFFFFFFFFu, q, off);
                c += __shfl_down_sync(0xFFFFFFFFu, c, off);
            }
            if (lid == 0) {
                double cn = (double)c;
                double mean = s / cn;
                double var = (q - s * s / cn) / (cn - 1.0);
                s_mean = (float)mean;
                s_invstd = (float)(1.0 / sqrt(var));
            }
        }
        __syncthreads();
    }

    float meanf = s_mean;
    float inv_std = s_invstd;

    const int OUT_N = FIXED_FRAMES * N_SEL * 3;
    int i = blockIdx.x * blockDim.x + threadIdx.x;
    if (i >= OUT_N) return;

    int f = i / (N_SEL * 3);
    int rem = i - f * (N_SEL * 3);
    int l = rem / 3;
    int c = rem - l * 3;
    int lm = c_sel[l];

    if (T >= FIXED_FRAMES) {
        // nearest-exact (f32 arithmetic matching the reference)
        float scale = (float)((double)T / (double)FIXED_FRAMES);
        float pos = ((float)f + 0.5f) * scale;
        int idx = (int)floorf(pos);
        if (idx < 0) idx = 0;
        if (idx > T - 1) idx = T - 1;
        float v = x[(size_t)idx * (N_LM * 3) + lm * 3 + c];
        out[i] = (v == v) ? (v - meanf) * inv_std : 0.0f;
    } else {
        // linear, align_corners=False
        float scale = (float)((double)T / (double)FIXED_FRAMES);
        float pos = ((float)f + 0.5f) * scale - 0.5f;
        pos = fminf(fmaxf(pos, 0.0f), (float)(T - 1));
        int i0 = (int)floorf(pos);
        int i1 = min(i0 + 1, T - 1);
        float w = pos - (float)i0;
        float v0 = x[(size_t)i0 * (N_LM * 3) + lm * 3 + c];
        float v1 = x[(size_t)i1 * (N_LM * 3) + lm * 3 + c];
        float y0 = (v0 == v0) ? (v0 - meanf) * inv_std : 0.0f;
        float y1 = (v1 == v1) ? (v1 - meanf) * inv_std : 0.0f;
        out[i] = (1.0f - w) * y0 + w * y1;
    }
}

extern "C" void kernel_launch(void* const* d_in, const int* in_sizes, int n_in,
                              void* d_out, int out_size) {
    const float* x = (const float*)d_in[0];
    float* out = (float*)d_out;

    long long ntotal = (long long)in_sizes[0];
    int T = (int)(ntotal / (N_LM * 3));
    long long nvec8 = ntotal >> 3;   // 256-bit chunks

    reduce_kernel<<<RED_BLOCKS, RED_THREADS>>>(x, nvec8, ntotal);

    const int OUT_N = FIXED_FRAMES * N_SEL * 3;  // 9630
    gather_kernel<<<(OUT_N + 1023) / 1024, 1024>>>(x, out, T);
}